// round 14
// baseline (speedup 1.0000x reference)
#include <cuda_runtime.h>
#include <cstdint>
#include <cstddef>
#include <math.h>

// Problem constants
#define NQ   2048
#define NS   65536
#define FD   512
#define KNN  16

// Tiling
#define BQ   128
#define BS   128
#define KC   32                  // fp32 K per chunk (4 x k8 mma steps)
#define NCH  (FD / KC)           // 16 chunks
#define SPLITS 18
#define SPS   3712               // 29 * 128 (last split clipped)
#define TPS   29
#define RS    36                 // smem row stride: {4g+tig} distinct mod 32
#define AS    (128 * RS)         // 4608 floats per operand tile
#define SDS   130                // dist tile stride (64 rows only)
#define NCAND 32                 // rescored candidates per query

typedef unsigned long long ull;
typedef uint32_t u32;

// ---------------- scratch ---------------------------------------------------
__device__ float g_q2[NQ];
__device__ float g_s2[NS];
__device__ float g_pd[NQ * SPLITS * 32];
__device__ int   g_pi[NQ * SPLITS * 32];

// ---------------- PTX helpers ------------------------------------------------
__device__ __forceinline__ u32 smem_u32(const void* p) {
    u32 a;
    asm("{ .reg .u64 t; cvta.to.shared.u64 t, %1; cvt.u32.u64 %0, t; }" : "=r"(a) : "l"(p));
    return a;
}
__device__ __forceinline__ void cpa16(u32 dst, const void* src) {
    asm volatile("cp.async.cg.shared.global [%0], [%1], 16;" :: "r"(dst), "l"(src));
}
#define CPA_COMMIT() asm volatile("cp.async.commit_group;" ::: "memory")
#define CPA_WAIT0()  asm volatile("cp.async.wait_group 0;" ::: "memory")

// m16n8k8 tf32 mma (base PTX ISA path, valid on compute_103). HW truncates
// fp32 operand bits to tf32 internally — fine for the candidate filter.
__device__ __forceinline__ void mma8(float (&c)[4], u32 a0, u32 a1, u32 a2, u32 a3,
                                     u32 b0, u32 b1) {
    asm volatile(
        "mma.sync.aligned.m16n8k8.row.col.f32.tf32.tf32.f32 "
        "{%0,%1,%2,%3}, {%4,%5,%6,%7}, {%8,%9}, {%0,%1,%2,%3};"
        : "+f"(c[0]), "+f"(c[1]), "+f"(c[2]), "+f"(c[3])
        : "r"(a0), "r"(a1), "r"(a2), "r"(a3), "r"(b0), "r"(b1));
}

__device__ __forceinline__ bool better(float d1, int i1, float d2, int i2) {
    return d1 < d2 || (d1 == d2 && i1 < i2);
}
__device__ __forceinline__ void insert16(float (&kd)[KNN], int (&ki)[KNN], float d, int i) {
    float cd = d; int ci = i;
#pragma unroll
    for (int j = 0; j < KNN; ++j) {
        bool b = better(cd, ci, kd[j], ki[j]);
        float td = kd[j]; int ti = ki[j];
        if (b) { kd[j] = cd; ki[j] = ci; cd = td; ci = ti; }
    }
}

// ---------------- kernel 0: row norms (bit-identical to passing R3/R12) -----
__global__ void knn_norms_kernel(const float* __restrict__ x, int nrows, int which) {
    int w    = (blockIdx.x * blockDim.x + threadIdx.x) >> 5;
    int lane = threadIdx.x & 31;
    if (w >= nrows) return;
    const float4* row = reinterpret_cast<const float4*>(x + (size_t)w * FD);
    float s = 0.f;
#pragma unroll
    for (int i = 0; i < FD / 4 / 32; ++i) {
        float4 v = row[lane + i * 32];
        s += v.x * v.x + v.y * v.y + v.z * v.z + v.w * v.w;
    }
#pragma unroll
    for (int o = 16; o > 0; o >>= 1) s += __shfl_xor_sync(0xffffffffu, s, o);
    if (lane == 0) { if (which) g_s2[w] = s; else g_q2[w] = s; }
}

// ---------------- kernel 1: TF32 mma.sync GEMM (candidate filter) -----------
// smem floats: [2 buf][A(AS), B(AS)] | sd(64*SDS) | q2s(128) | s2s(128)
#define SMEM_FLOATS (4 * AS + 64 * SDS + BQ + BS)

__global__ __launch_bounds__(256, 2)
void knn_mma_kernel(const float* __restrict__ Q, const float* __restrict__ S) {
    extern __shared__ float smem[];
    float* sd  = smem + 4 * AS;
    float* q2s = sd + 64 * SDS;
    float* s2s = q2s + BQ;

    const int tid  = threadIdx.x;
    const int wid  = tid >> 5, lane = tid & 31;
    const int wm   = wid >> 2, wn = wid & 3;        // 2x4 warp grid (64x32 warp tile)
    const int g    = lane >> 2, tig = lane & 3;
    const int qb   = blockIdx.x, sb = blockIdx.y;
    const int q0   = qb * BQ;
    const int sBase = sb * SPS;
    const u32 smb  = smem_u32(smem);

    if (tid < BQ) q2s[tid] = g_q2[q0 + tid];

    // staging geometry: 4 x 16B per thread per operand per chunk (KC=32)
    int rowv[4], kgv[4]; u32 soff[4];
#pragma unroll
    for (int i = 0; i < 4; ++i) {
        int idx = tid + i * 256;       // 0..1023
        rowv[i] = idx >> 3;            // 0..127
        kgv[i]  = (idx & 7) * 4;       // 0..28
        soff[i] = (u32)(rowv[i] * RS + kgv[i]) * 4u;  // byte offset in tile
    }

    float kd[KNN]; int ki[KNN];
#pragma unroll
    for (int j = 0; j < KNN; ++j) { kd[j] = __int_as_float(0x7f800000); ki[j] = 0x7fffffff; }

    // top-k roles: tid<128 owns query rows 0..63, tid>=128 owns 64..127
    const int qrow = ((tid & 128) ? 64 : 0) + ((tid & 127) >> 1);
    const int hh   = tid & 1;
    const int grp  = tid >> 7;         // scan group (0 or 1)

    // ---- preload tile 0, chunk 0 into buffer 0 ----
#pragma unroll
    for (int i = 0; i < 4; ++i) {
        cpa16(smb + soff[i],            Q + (size_t)(q0 + rowv[i]) * FD + kgv[i]);
        cpa16(smb + AS * 4 + soff[i],   S + (size_t)(sBase + rowv[i]) * FD + kgv[i]);
    }
    CPA_COMMIT();
    CPA_WAIT0();
    __syncthreads();

    const float q2v = q2s[qrow];       // fixed per thread

    int buf = 0;

    for (int t = 0; t < TPS; ++t) {
        const int s0 = sBase + t * BS;
        if (s0 >= NS) break;
        if (tid < BS) s2s[tid] = g_s2[s0 + tid];

        float acc[4][4][4];
#pragma unroll
        for (int mt = 0; mt < 4; ++mt)
#pragma unroll
            for (int nt = 0; nt < 4; ++nt)
#pragma unroll
                for (int r = 0; r < 4; ++r) acc[mt][nt][r] = 0.f;

        for (int c = 0; c < NCH; ++c) {
            const bool hasNext = (c < NCH - 1) || ((t + 1 < TPS) && (s0 + BS < NS));
            int ccn, s0n;
            if (c < NCH - 1) { ccn = (c + 1) * KC; s0n = s0; }
            else             { ccn = 0;            s0n = s0 + BS; }

            // ---- async-stage next chunk into the other buffer ----
            if (hasNext) {
                const u32 db = smb + (u32)(buf ^ 1) * (2u * AS * 4u);
#pragma unroll
                for (int i = 0; i < 4; ++i) {
                    cpa16(db + soff[i],          Q + (size_t)(q0 + rowv[i]) * FD + ccn + kgv[i]);
                    cpa16(db + AS * 4 + soff[i], S + (size_t)(s0n + rowv[i]) * FD + ccn + kgv[i]);
                }
                CPA_COMMIT();
            }

            // ---- consume current buffer: 4 k8 steps, 16 mma each ----
            {
                const float* bb = smem + buf * 2 * AS;
                const u32* uA = (const u32*)(bb)      + (wm * 64) * RS;
                const u32* uB = (const u32*)(bb + AS) + (wn * 32) * RS;
#pragma unroll
                for (int ks = 0; ks < 4; ++ks) {
                    const int kb = ks * 8 + tig;
                    u32 bf[4][2];
#pragma unroll
                    for (int nt = 0; nt < 4; ++nt) {
                        int ba = (nt * 8 + g) * RS + kb;
                        bf[nt][0] = uB[ba]; bf[nt][1] = uB[ba + 4];
                    }
#pragma unroll
                    for (int mt = 0; mt < 4; ++mt) {
                        int aa = (mt * 16 + g) * RS + kb;
                        u32 a0 = uA[aa],     a1 = uA[aa + 8 * RS];
                        u32 a2 = uA[aa + 4], a3 = uA[aa + 8 * RS + 4];
#pragma unroll
                        for (int nt = 0; nt < 4; ++nt)
                            mma8(acc[mt][nt], a0, a1, a2, a3, bf[nt][0], bf[nt][1]);
                    }
                }
            }

            if (hasNext) CPA_WAIT0();
            __syncthreads();
            if (hasNext) buf ^= 1;
        }

        // ---- two-pass spill + approx top-16 scan (sd holds 64 rows) ----
#pragma unroll
        for (int h = 0; h < 2; ++h) {
            if (wm == h) {
#pragma unroll
                for (int mt = 0; mt < 4; ++mt) {
                    int rowL = mt * 16 + g;
#pragma unroll
                    for (int nt = 0; nt < 4; ++nt) {
                        int col = wn * 32 + nt * 8 + 2 * tig;
                        *(float2*)(sd + rowL * SDS + col)       = make_float2(acc[mt][nt][0], acc[mt][nt][1]);
                        *(float2*)(sd + (rowL + 8) * SDS + col) = make_float2(acc[mt][nt][2], acc[mt][nt][3]);
                    }
                }
            }
            __syncthreads();
            if (grp == h) {
                const int rl = (tid & 127) >> 1;
                const float* drow = sd + rl * SDS + hh * 64;
                const float* s2p  = s2s + hh * 64;
#pragma unroll 8
                for (int j = 0; j < 64; ++j) {
                    float d2 = fmaxf(q2v + s2p[j] - 2.f * drow[j], 1e-12f);
                    int idx = s0 + hh * 64 + j;
                    if (better(d2, idx, kd[KNN - 1], ki[KNN - 1])) insert16(kd, ki, d2, idx);
                }
            }
            __syncthreads();
        }
    }

    // ---- emit per-(query, split) candidate lists ----
    {
        size_t b = ((size_t)(q0 + qrow) * SPLITS + sb) * 32 + (size_t)hh * 16;
#pragma unroll
        for (int r = 0; r < KNN; ++r) { g_pd[b + r] = kd[r]; g_pi[b + r] = ki[r]; }
    }
}

// ---------------- kernel 2: approx cut -> R3-exact fp32 rescore -------------
__global__ void knn_merge_kernel(const float* __restrict__ Q,
                                 const float* __restrict__ S,
                                 float* __restrict__ out) {
    int gw   = (blockIdx.x * blockDim.x + threadIdx.x) >> 5;  // query id
    int lane = threadIdx.x & 31;
    if (gw >= NQ) return;
    const float* pd = g_pd + (size_t)gw * (SPLITS * 32);
    const int*   pi = g_pi + (size_t)gw * (SPLITS * 32);

    // SPLITS*32 = 576 approx candidates -> packed (d2_bits<<32)|idx
    ull key[SPLITS];
#pragma unroll
    for (int j = 0; j < SPLITS; ++j) {
        int c = lane + j * 32;
        key[j] = ((ull)__float_as_uint(pd[c]) << 32) | (u32)pi[c];
    }
    // local ascending odd-even sort
#pragma unroll
    for (int p = 0; p < SPLITS; ++p)
#pragma unroll
        for (int a = (p & 1); a + 1 < SPLITS; a += 2)
            if (key[a + 1] < key[a]) { ull tk = key[a]; key[a] = key[a + 1]; key[a + 1] = tk; }

    // extract approx top-32; lane r keeps candidate r
    u32 myidx = 0u;
#pragma unroll
    for (int r = 0; r < NCAND; ++r) {
        ull m = key[0];
#pragma unroll
        for (int o = 16; o; o >>= 1) {
            ull v = __shfl_xor_sync(0xffffffffu, m, o);
            if (v < m) m = v;
        }
        if (key[0] == m) {                 // unique winner shifts its list
#pragma unroll
            for (int a = 0; a < SPLITS - 1; ++a) key[a] = key[a + 1];
            key[SPLITS - 1] = ~0ull;
        }
        if (lane == r) myidx = (u32)m;
    }

    // ---- rescore: one candidate per lane, sequential fp32 FMA over k ----
    const float* qp = Q + (size_t)gw * FD;
    const float* sp = S + (size_t)myidx * FD;
    float dot = 0.f;
#pragma unroll 4
    for (int k = 0; k < FD; k += 4) {
        float4 qv = *(const float4*)(qp + k);
        float4 sv = *(const float4*)(sp + k);
        dot = fmaf(qv.x, sv.x, dot);
        dot = fmaf(qv.y, sv.y, dot);
        dot = fmaf(qv.z, sv.z, dot);
        dot = fmaf(qv.w, sv.w, dot);
    }
    const float q2v = g_q2[gw];
    const float s2v = g_s2[myidx];
    float d2 = fmaxf(q2v + s2v - 2.f * dot, 1e-12f);

    // ---- exact top-16 of the 32 by (d2, idx) ----
    ull k2 = ((ull)__float_as_uint(d2) << 32) | myidx;
    float find = 0.f; u32 fini = 0u;
#pragma unroll
    for (int r = 0; r < KNN; ++r) {
        ull m = k2;
#pragma unroll
        for (int o = 16; o; o >>= 1) {
            ull v = __shfl_xor_sync(0xffffffffu, m, o);
            if (v < m) m = v;
        }
        if (k2 == m) k2 = ~0ull;           // remove winner
        if (lane == r) { find = __uint_as_float((u32)(m >> 32)); fini = (u32)m; }
    }

    // ---- weights (same formula/precision as R3) ----
    float dist = sqrtf(find);
    float sim  = (lane < KNN) ? 1.f / (dist + 1e-6f) : 0.f;
    float s = sim;
#pragma unroll
    for (int o = 16; o; o >>= 1) s += __shfl_xor_sync(0xffffffffu, s, o);
    if (lane < KNN) {
        out[(size_t)gw * KNN + lane] = (float)fini;
        out[(size_t)NQ * KNN + (size_t)gw * KNN + lane] = sim / s;
    }
}

// ---------------- launch ------------------------------------------------------
extern "C" void kernel_launch(void* const* d_in, const int* in_sizes, int n_in,
                              void* d_out, int out_size) {
    (void)in_sizes; (void)n_in; (void)out_size;
    const float* Q = (const float*)d_in[0];
    const float* S = (const float*)d_in[1];
    float* out = (float*)d_out;

    const int smem_bytes = SMEM_FLOATS * 4;   // 108032 B -> 2 CTAs/SM
    cudaFuncSetAttribute(knn_mma_kernel,
                         cudaFuncAttributeMaxDynamicSharedMemorySize, smem_bytes);

    knn_norms_kernel<<<(NQ * 32) / 256, 256>>>(Q, NQ, 0);
    knn_norms_kernel<<<(NS * 32) / 256, 256>>>(S, NS, 1);

    dim3 grid(NQ / BQ, SPLITS);
    knn_mma_kernel<<<grid, 256, smem_bytes>>>(Q, S);

    knn_merge_kernel<<<NQ / 8, 256>>>(Q, S, out);
}

// round 16
// speedup vs baseline: 1.7553x; 1.7553x over previous
#include <cuda_runtime.h>
#include <cstdint>
#include <cstddef>
#include <math.h>

// Problem constants
#define NQ   2048
#define NS   65536
#define FD   512
#define KNN  16

// Tiling
#define BQ   128
#define BS   128
#define KC   32                  // fp32 K per chunk (4 x k8 mma steps)
#define NCH  (FD / KC)           // 16 chunks
#define SPLITS 9
#define SPS   7296               // 57 * 128
#define TPS   57
#define RS    36                 // smem row stride: conflict-free fragment LDS
#define AS    (128 * RS)         // 4608 floats per operand tile
#define SDS   130                // dist tile stride
#define NCAND 32                 // rescored candidates per query
#define NTHR  512
#define CPL   ((SPLITS * 64) / 32)   // merge keys per lane = 18

typedef unsigned long long ull;
typedef uint32_t u32;

// ---------------- scratch ---------------------------------------------------
__device__ float g_q2[NQ];
__device__ float g_s2[NS];
__device__ float g_pd[NQ * SPLITS * 64];
__device__ int   g_pi[NQ * SPLITS * 64];

// ---------------- PTX helpers ------------------------------------------------
__device__ __forceinline__ u32 smem_u32(const void* p) {
    u32 a;
    asm("{ .reg .u64 t; cvta.to.shared.u64 t, %1; cvt.u32.u64 %0, t; }" : "=r"(a) : "l"(p));
    return a;
}
__device__ __forceinline__ void cpa16(u32 dst, const void* src) {
    asm volatile("cp.async.cg.shared.global [%0], [%1], 16;" :: "r"(dst), "l"(src));
}
#define CPA_COMMIT() asm volatile("cp.async.commit_group;" ::: "memory")
#define CPA_WAIT0()  asm volatile("cp.async.wait_group 0;" ::: "memory")

// m16n8k8 tf32 mma (base PTX ISA path). HW reads tf32 bit-fields from the
// fp32 container (effective RZ truncation) — fine for the candidate filter.
__device__ __forceinline__ void mma8(float (&c)[4], u32 a0, u32 a1, u32 a2, u32 a3,
                                     u32 b0, u32 b1) {
    asm volatile(
        "mma.sync.aligned.m16n8k8.row.col.f32.tf32.tf32.f32 "
        "{%0,%1,%2,%3}, {%4,%5,%6,%7}, {%8,%9}, {%0,%1,%2,%3};"
        : "+f"(c[0]), "+f"(c[1]), "+f"(c[2]), "+f"(c[3])
        : "r"(a0), "r"(a1), "r"(a2), "r"(a3), "r"(b0), "r"(b1));
}

__device__ __forceinline__ bool better(float d1, int i1, float d2, int i2) {
    return d1 < d2 || (d1 == d2 && i1 < i2);
}
__device__ __forceinline__ void insert16(float (&kd)[KNN], int (&ki)[KNN], float d, int i) {
    float cd = d; int ci = i;
#pragma unroll
    for (int j = 0; j < KNN; ++j) {
        bool b = better(cd, ci, kd[j], ki[j]);
        float td = kd[j]; int ti = ki[j];
        if (b) { kd[j] = cd; ki[j] = ci; cd = td; ci = ti; }
    }
}

// ---------------- kernel 0: row norms (bit-identical to passing R3/R12) -----
__global__ void knn_norms_kernel(const float* __restrict__ x, int nrows, int which) {
    int w    = (blockIdx.x * blockDim.x + threadIdx.x) >> 5;
    int lane = threadIdx.x & 31;
    if (w >= nrows) return;
    const float4* row = reinterpret_cast<const float4*>(x + (size_t)w * FD);
    float s = 0.f;
#pragma unroll
    for (int i = 0; i < FD / 4 / 32; ++i) {
        float4 v = row[lane + i * 32];
        s += v.x * v.x + v.y * v.y + v.z * v.z + v.w * v.w;
    }
#pragma unroll
    for (int o = 16; o > 0; o >>= 1) s += __shfl_xor_sync(0xffffffffu, s, o);
    if (lane == 0) { if (which) g_s2[w] = s; else g_q2[w] = s; }
}

// ---------------- kernel 1: TF32 mma.sync GEMM (candidate filter) -----------
// 512 threads, 4x4 warp grid, 32x32 warp tile, cp.async double buffer.
// smem floats: [2 buf][A(AS), B(AS)] | sd(128*SDS) | q2s(128) | s2s(128)
#define SMEM_FLOATS (4 * AS + BQ * SDS + BQ + BS)

__global__ __launch_bounds__(NTHR, 1)
void knn_mma_kernel(const float* __restrict__ Q, const float* __restrict__ S) {
    extern __shared__ float smem[];
    float* sd  = smem + 4 * AS;
    float* q2s = sd + BQ * SDS;
    float* s2s = q2s + BQ;

    const int tid  = threadIdx.x;
    const int wid  = tid >> 5, lane = tid & 31;
    const int wm   = wid & 3, wn = wid >> 2;        // 4x4 warp grid (32x32 tile)
    const int g    = lane >> 2, tig = lane & 3;
    const int qb   = blockIdx.x, sb = blockIdx.y;
    const int q0   = qb * BQ;
    const int sBase = sb * SPS;
    const u32 smb  = smem_u32(smem);

    if (tid < BQ) q2s[tid] = g_q2[q0 + tid];

    // staging geometry: 2 x 16B per thread per operand per chunk (KC=32)
    int rowv[2], kgv[2]; u32 soff[2];
#pragma unroll
    for (int i = 0; i < 2; ++i) {
        int idx = tid + i * NTHR;      // 0..1023
        rowv[i] = idx >> 3;            // 0..127
        kgv[i]  = (idx & 7) * 4;       // 0..28
        soff[i] = (u32)(rowv[i] * RS + kgv[i]) * 4u;
    }

    float kd[KNN]; int ki[KNN];
#pragma unroll
    for (int j = 0; j < KNN; ++j) { kd[j] = __int_as_float(0x7f800000); ki[j] = 0x7fffffff; }

    // top-k roles: 4 threads per query row, each scans 32 columns
    const int qrow = tid >> 2;
    const int qq   = tid & 3;

    // ---- preload tile 0, chunk 0 into buffer 0 ----
#pragma unroll
    for (int i = 0; i < 2; ++i) {
        cpa16(smb + soff[i],          Q + (size_t)(q0 + rowv[i]) * FD + kgv[i]);
        cpa16(smb + AS * 4 + soff[i], S + (size_t)(sBase + rowv[i]) * FD + kgv[i]);
    }
    CPA_COMMIT();
    CPA_WAIT0();
    __syncthreads();

    const float q2v = q2s[qrow];

    int buf = 0;

    for (int t = 0; t < TPS; ++t) {
        const int s0 = sBase + t * BS;
        if (s0 >= NS) break;
        if (tid < BS) s2s[tid] = g_s2[s0 + tid];

        float acc[2][4][4];
#pragma unroll
        for (int mt = 0; mt < 2; ++mt)
#pragma unroll
            for (int nt = 0; nt < 4; ++nt)
#pragma unroll
                for (int r = 0; r < 4; ++r) acc[mt][nt][r] = 0.f;

        for (int c = 0; c < NCH; ++c) {
            const bool hasNext = (c < NCH - 1) || ((t + 1 < TPS) && (s0 + BS < NS));
            int ccn, s0n;
            if (c < NCH - 1) { ccn = (c + 1) * KC; s0n = s0; }
            else             { ccn = 0;            s0n = s0 + BS; }

            // ---- async-stage next chunk into the other buffer ----
            if (hasNext) {
                const u32 db = smb + (u32)(buf ^ 1) * (2u * AS * 4u);
#pragma unroll
                for (int i = 0; i < 2; ++i) {
                    cpa16(db + soff[i],          Q + (size_t)(q0 + rowv[i]) * FD + ccn + kgv[i]);
                    cpa16(db + AS * 4 + soff[i], S + (size_t)(s0n + rowv[i]) * FD + ccn + kgv[i]);
                }
                CPA_COMMIT();
            }

            // ---- consume current buffer: 4 k8 steps, 8 mma each ----
            {
                const float* bb = smem + buf * 2 * AS;
                const u32* uA = (const u32*)(bb)      + (wm * 32) * RS;
                const u32* uB = (const u32*)(bb + AS) + (wn * 32) * RS;
#pragma unroll
                for (int ks = 0; ks < 4; ++ks) {
                    const int kb = ks * 8 + tig;
                    u32 bf[4][2];
#pragma unroll
                    for (int nt = 0; nt < 4; ++nt) {
                        int ba = (nt * 8 + g) * RS + kb;
                        bf[nt][0] = uB[ba]; bf[nt][1] = uB[ba + 4];
                    }
#pragma unroll
                    for (int mt = 0; mt < 2; ++mt) {
                        int aa = (mt * 16 + g) * RS + kb;
                        u32 a0 = uA[aa],     a1 = uA[aa + 8 * RS];
                        u32 a2 = uA[aa + 4], a3 = uA[aa + 8 * RS + 4];
#pragma unroll
                        for (int nt = 0; nt < 4; ++nt)
                            mma8(acc[mt][nt], a0, a1, a2, a3, bf[nt][0], bf[nt][1]);
                    }
                }
            }

            if (hasNext) CPA_WAIT0();
            __syncthreads();
            if (hasNext) buf ^= 1;
        }

        // ---- spill accumulators to dist tile ----
#pragma unroll
        for (int mt = 0; mt < 2; ++mt) {
            int row = wm * 32 + mt * 16 + g;
#pragma unroll
            for (int nt = 0; nt < 4; ++nt) {
                int col = wn * 32 + nt * 8 + 2 * tig;
                *(float2*)(sd + row * SDS + col)       = make_float2(acc[mt][nt][0], acc[mt][nt][1]);
                *(float2*)(sd + (row + 8) * SDS + col) = make_float2(acc[mt][nt][2], acc[mt][nt][3]);
            }
        }
        __syncthreads();

        // ---- approx top-16: 4 threads per query, 32 candidates each ----
        {
            const float* drow = sd + qrow * SDS + qq * 32;
            const float* s2p  = s2s + qq * 32;
#pragma unroll 8
            for (int j = 0; j < 32; ++j) {
                float d2 = fmaxf(q2v + s2p[j] - 2.f * drow[j], 1e-12f);
                int idx = s0 + qq * 32 + j;
                if (better(d2, idx, kd[KNN - 1], ki[KNN - 1])) insert16(kd, ki, d2, idx);
            }
        }
        __syncthreads();
    }

    // ---- emit per-(query, split, quarter) candidate lists ----
    {
        size_t b = ((size_t)(q0 + qrow) * SPLITS + sb) * 64 + (size_t)qq * 16;
#pragma unroll
        for (int r = 0; r < KNN; ++r) { g_pd[b + r] = kd[r]; g_pi[b + r] = ki[r]; }
    }
}

// ---------------- kernel 2: approx cut -> R3-exact fp32 rescore -------------
__global__ void knn_merge_kernel(const float* __restrict__ Q,
                                 const float* __restrict__ S,
                                 float* __restrict__ out) {
    int gw   = (blockIdx.x * blockDim.x + threadIdx.x) >> 5;  // query id
    int lane = threadIdx.x & 31;
    if (gw >= NQ) return;
    const float* pd = g_pd + (size_t)gw * (SPLITS * 64);
    const int*   pi = g_pi + (size_t)gw * (SPLITS * 64);

    // SPLITS*64 = 576 approx candidates -> packed (d2_bits<<32)|idx
    ull key[CPL];
#pragma unroll
    for (int j = 0; j < CPL; ++j) {
        int c = lane + j * 32;
        key[j] = ((ull)__float_as_uint(pd[c]) << 32) | (u32)pi[c];
    }
    // local ascending odd-even sort
#pragma unroll
    for (int p = 0; p < CPL; ++p)
#pragma unroll
        for (int a = (p & 1); a + 1 < CPL; a += 2)
            if (key[a + 1] < key[a]) { ull tk = key[a]; key[a] = key[a + 1]; key[a + 1] = tk; }

    // extract approx top-32; lane r keeps candidate r
    u32 myidx = 0u;
#pragma unroll
    for (int r = 0; r < NCAND; ++r) {
        ull m = key[0];
#pragma unroll
        for (int o = 16; o; o >>= 1) {
            ull v = __shfl_xor_sync(0xffffffffu, m, o);
            if (v < m) m = v;
        }
        if (key[0] == m) {                 // unique winner shifts its list
#pragma unroll
            for (int a = 0; a < CPL - 1; ++a) key[a] = key[a + 1];
            key[CPL - 1] = ~0ull;
        }
        if (lane == r) myidx = (u32)m;
    }

    // ---- rescore: one candidate per lane, sequential fp32 FMA over k ----
    const float* qp = Q + (size_t)gw * FD;
    const float* sp = S + (size_t)myidx * FD;
    float dot = 0.f;
#pragma unroll 4
    for (int k = 0; k < FD; k += 4) {
        float4 qv = *(const float4*)(qp + k);
        float4 sv = *(const float4*)(sp + k);
        dot = fmaf(qv.x, sv.x, dot);
        dot = fmaf(qv.y, sv.y, dot);
        dot = fmaf(qv.z, sv.z, dot);
        dot = fmaf(qv.w, sv.w, dot);
    }
    const float q2v = g_q2[gw];
    const float s2v = g_s2[myidx];
    float d2 = fmaxf(q2v + s2v - 2.f * dot, 1e-12f);

    // ---- exact top-16 of the 32 by (d2, idx) ----
    ull k2 = ((ull)__float_as_uint(d2) << 32) | myidx;
    float find = 0.f; u32 fini = 0u;
#pragma unroll
    for (int r = 0; r < KNN; ++r) {
        ull m = k2;
#pragma unroll
        for (int o = 16; o; o >>= 1) {
            ull v = __shfl_xor_sync(0xffffffffu, m, o);
            if (v < m) m = v;
        }
        if (k2 == m) k2 = ~0ull;           // remove winner
        if (lane == r) { find = __uint_as_float((u32)(m >> 32)); fini = (u32)m; }
    }

    // ---- weights (same formula/precision as R3) ----
    float dist = sqrtf(find);
    float sim  = (lane < KNN) ? 1.f / (dist + 1e-6f) : 0.f;
    float s = sim;
#pragma unroll
    for (int o = 16; o; o >>= 1) s += __shfl_xor_sync(0xffffffffu, s, o);
    if (lane < KNN) {
        out[(size_t)gw * KNN + lane] = (float)fini;
        out[(size_t)NQ * KNN + (size_t)gw * KNN + lane] = sim / s;
    }
}

// ---------------- launch ------------------------------------------------------
extern "C" void kernel_launch(void* const* d_in, const int* in_sizes, int n_in,
                              void* d_out, int out_size) {
    (void)in_sizes; (void)n_in; (void)out_size;
    const float* Q = (const float*)d_in[0];
    const float* S = (const float*)d_in[1];
    float* out = (float*)d_out;

    const int smem_bytes = SMEM_FLOATS * 4;   // ~141 KB -> 1 CTA/SM, 16 warps
    cudaFuncSetAttribute(knn_mma_kernel,
                         cudaFuncAttributeMaxDynamicSharedMemorySize, smem_bytes);

    knn_norms_kernel<<<(NQ * 32) / 256, 256>>>(Q, NQ, 0);
    knn_norms_kernel<<<(NS * 32) / 256, 256>>>(S, NS, 1);

    dim3 grid(NQ / BQ, SPLITS);
    knn_mma_kernel<<<grid, NTHR, smem_bytes>>>(Q, S);

    knn_merge_kernel<<<NQ / 8, 256>>>(Q, S, out);
}

// round 17
// speedup vs baseline: 1.8556x; 1.0571x over previous
#include <cuda_runtime.h>
#include <cstdint>
#include <cstddef>
#include <math.h>

// Problem constants
#define NQ   2048
#define NS   65536
#define FD   512
#define KNN  16

// Tiling
#define BQ   128
#define BS   128
#define KC   32                  // fp32 K per chunk (2 x k16 bf16 mma steps)
#define NCH  (FD / KC)           // 16 chunks
#define SPLITS 9
#define SPS   7296               // 57 * 128
#define TPS   57
#define RS2   20                 // smem row stride in u32 (bf16 pairs): conflict-free frags
#define ASU   (128 * RS2)        // 2560 u32 per operand tile
#define SDS   130                // dist tile stride
#define NCAND 32                 // rescored candidates per query
#define NTHR  512
#define CPL   ((SPLITS * 64) / 32)   // merge keys per lane = 18

typedef unsigned long long ull;
typedef uint32_t u32;

// ---------------- scratch ---------------------------------------------------
__device__ float g_q2[NQ];
__device__ float g_s2[NS];
__device__ float g_pd[NQ * SPLITS * 64];
__device__ int   g_pi[NQ * SPLITS * 64];

// ---------------- helpers ---------------------------------------------------
__device__ __forceinline__ u32 bfx2(float hi, float lo) {
    u32 d; asm("cvt.rn.bf16x2.f32 %0, %1, %2;" : "=r"(d) : "f"(hi), "f"(lo));
    return d;
}
// m16n8k16 bf16 mma (base PTX ISA, legacy tensor path) — 2048 MAC/instr
__device__ __forceinline__ void mma16(float (&c)[4], u32 a0, u32 a1, u32 a2, u32 a3,
                                      u32 b0, u32 b1) {
    asm volatile(
        "mma.sync.aligned.m16n8k16.row.col.f32.bf16.bf16.f32 "
        "{%0,%1,%2,%3}, {%4,%5,%6,%7}, {%8,%9}, {%0,%1,%2,%3};"
        : "+f"(c[0]), "+f"(c[1]), "+f"(c[2]), "+f"(c[3])
        : "r"(a0), "r"(a1), "r"(a2), "r"(a3), "r"(b0), "r"(b1));
}

__device__ __forceinline__ bool better(float d1, int i1, float d2, int i2) {
    return d1 < d2 || (d1 == d2 && i1 < i2);
}
__device__ __forceinline__ void insert16(float (&kd)[KNN], int (&ki)[KNN], float d, int i) {
    float cd = d; int ci = i;
#pragma unroll
    for (int j = 0; j < KNN; ++j) {
        bool b = better(cd, ci, kd[j], ki[j]);
        float td = kd[j]; int ti = ki[j];
        if (b) { kd[j] = cd; ki[j] = ci; cd = td; ci = ti; }
    }
}

// ---------------- kernel 0: row norms (bit-identical to passing R3/R12) -----
__global__ void knn_norms_kernel(const float* __restrict__ x, int nrows, int which) {
    int w    = (blockIdx.x * blockDim.x + threadIdx.x) >> 5;
    int lane = threadIdx.x & 31;
    if (w >= nrows) return;
    const float4* row = reinterpret_cast<const float4*>(x + (size_t)w * FD);
    float s = 0.f;
#pragma unroll
    for (int i = 0; i < FD / 4 / 32; ++i) {
        float4 v = row[lane + i * 32];
        s += v.x * v.x + v.y * v.y + v.z * v.z + v.w * v.w;
    }
#pragma unroll
    for (int o = 16; o > 0; o >>= 1) s += __shfl_xor_sync(0xffffffffu, s, o);
    if (lane == 0) { if (which) g_s2[w] = s; else g_q2[w] = s; }
}

// ---------------- kernel 1: bf16 mma.sync GEMM (candidate filter) -----------
// 512 threads, 4x4 warp grid (32x32 warp tile), register double-buffer staging
// with on-the-fly fp32 -> bf16x2 conversion.
// smem: [2 buf][A(ASU), B(ASU)] u32 | sd(128*SDS) f32 | q2s(128) | s2s(128)
#define SMEM_FLOATS (4 * ASU + BQ * SDS + BQ + BS)

__global__ __launch_bounds__(NTHR, 1)
void knn_mma_kernel(const float* __restrict__ Q, const float* __restrict__ S) {
    extern __shared__ float smem[];
    u32*   st  = reinterpret_cast<u32*>(smem);
    float* sd  = smem + 4 * ASU;
    float* q2s = sd + BQ * SDS;
    float* s2s = q2s + BQ;

    const int tid  = threadIdx.x;
    const int wid  = tid >> 5, lane = tid & 31;
    const int wm   = wid & 3, wn = wid >> 2;        // 4x4 warp grid (32x32 tile)
    const int g    = lane >> 2, tig = lane & 3;
    const int qb   = blockIdx.x, sb = blockIdx.y;
    const int q0   = qb * BQ;
    const int sBase = sb * SPS;

    if (tid < BQ) q2s[tid] = g_q2[q0 + tid];

    // staging geometry: 2 x float4 per thread per operand per chunk (KC=32)
    int rowv[2], kgv[2], dstv[2];
#pragma unroll
    for (int i = 0; i < 2; ++i) {
        int idx = tid + i * NTHR;      // 0..1023
        rowv[i] = idx >> 3;            // 0..127
        kgv[i]  = (idx & 7) * 4;       // fp32 col 0..28
        dstv[i] = rowv[i] * RS2 + (idx & 7) * 2;   // u32 (bf16-pair) index
    }

    float kd[KNN]; int ki[KNN];
#pragma unroll
    for (int j = 0; j < KNN; ++j) { kd[j] = __int_as_float(0x7f800000); ki[j] = 0x7fffffff; }

    // top-k roles: 4 threads per query row, each scans 32 columns
    const int qrow = tid >> 2;
    const int qq   = tid & 3;

    // ---- preload tile 0, chunk 0 into buffer 0 ----
#pragma unroll
    for (int i = 0; i < 2; ++i) {
        float4 a = *(const float4*)(Q + (size_t)(q0 + rowv[i]) * FD + kgv[i]);
        float4 b = *(const float4*)(S + (size_t)(sBase + rowv[i]) * FD + kgv[i]);
        *(uint2*)(st + dstv[i])       = make_uint2(bfx2(a.y, a.x), bfx2(a.w, a.z));
        *(uint2*)(st + ASU + dstv[i]) = make_uint2(bfx2(b.y, b.x), bfx2(b.w, b.z));
    }
    __syncthreads();

    const float q2v = q2s[qrow];

    int buf = 0;

    for (int t = 0; t < TPS; ++t) {
        const int s0 = sBase + t * BS;
        if (s0 >= NS) break;
        if (tid < BS) s2s[tid] = g_s2[s0 + tid];

        float acc[2][4][4];
#pragma unroll
        for (int mt = 0; mt < 2; ++mt)
#pragma unroll
            for (int nt = 0; nt < 4; ++nt)
#pragma unroll
                for (int r = 0; r < 4; ++r) acc[mt][nt][r] = 0.f;

        for (int c = 0; c < NCH; ++c) {
            const bool hasNext = (c < NCH - 1) || ((t + 1 < TPS) && (s0 + BS < NS));
            int ccn, s0n;
            if (c < NCH - 1) { ccn = (c + 1) * KC; s0n = s0; }
            else             { ccn = 0;            s0n = s0 + BS; }

            // ---- issue next-chunk global loads (register double buffer) ----
            float4 ra[2], rb[2];
            if (hasNext) {
#pragma unroll
                for (int i = 0; i < 2; ++i) {
                    ra[i] = *(const float4*)(Q + (size_t)(q0 + rowv[i]) * FD + ccn + kgv[i]);
                    rb[i] = *(const float4*)(S + (size_t)(s0n + rowv[i]) * FD + ccn + kgv[i]);
                }
            }

            // ---- consume current buffer: 2 k16 steps, 8 mma each ----
            {
                const u32* uA = st + buf * 2 * ASU + (wm * 32) * RS2;
                const u32* uB = st + buf * 2 * ASU + ASU + (wn * 32) * RS2;
#pragma unroll
                for (int ks = 0; ks < 2; ++ks) {
                    const int kofs = ks * 8 + tig;
                    u32 bf[4][2];
#pragma unroll
                    for (int nt = 0; nt < 4; ++nt) {
                        int ba = (nt * 8 + g) * RS2 + kofs;
                        bf[nt][0] = uB[ba]; bf[nt][1] = uB[ba + 4];
                    }
#pragma unroll
                    for (int mt = 0; mt < 2; ++mt) {
                        int aa = (mt * 16 + g) * RS2 + kofs;
                        u32 a0 = uA[aa],     a1 = uA[aa + 8 * RS2];
                        u32 a2 = uA[aa + 4], a3 = uA[aa + 8 * RS2 + 4];
#pragma unroll
                        for (int nt = 0; nt < 4; ++nt)
                            mma16(acc[mt][nt], a0, a1, a2, a3, bf[nt][0], bf[nt][1]);
                    }
                }
            }

            // ---- convert + store next chunk into the other buffer ----
            if (hasNext) {
                u32* db = st + (buf ^ 1) * 2 * ASU;
#pragma unroll
                for (int i = 0; i < 2; ++i) {
                    *(uint2*)(db + dstv[i])       = make_uint2(bfx2(ra[i].y, ra[i].x), bfx2(ra[i].w, ra[i].z));
                    *(uint2*)(db + ASU + dstv[i]) = make_uint2(bfx2(rb[i].y, rb[i].x), bfx2(rb[i].w, rb[i].z));
                }
            }
            __syncthreads();
            if (hasNext) buf ^= 1;
        }

        // ---- spill accumulators to dist tile ----
#pragma unroll
        for (int mt = 0; mt < 2; ++mt) {
            int row = wm * 32 + mt * 16 + g;
#pragma unroll
            for (int nt = 0; nt < 4; ++nt) {
                int col = wn * 32 + nt * 8 + 2 * tig;
                *(float2*)(sd + row * SDS + col)       = make_float2(acc[mt][nt][0], acc[mt][nt][1]);
                *(float2*)(sd + (row + 8) * SDS + col) = make_float2(acc[mt][nt][2], acc[mt][nt][3]);
            }
        }
        __syncthreads();

        // ---- approx top-16: 4 threads per query, 32 candidates each ----
        {
            const float* drow = sd + qrow * SDS + qq * 32;
            const float* s2p  = s2s + qq * 32;
#pragma unroll 8
            for (int j = 0; j < 32; ++j) {
                float d2 = fmaxf(q2v + s2p[j] - 2.f * drow[j], 1e-12f);
                int idx = s0 + qq * 32 + j;
                if (better(d2, idx, kd[KNN - 1], ki[KNN - 1])) insert16(kd, ki, d2, idx);
            }
        }
        __syncthreads();
    }

    // ---- emit per-(query, split, quarter) candidate lists ----
    {
        size_t b = ((size_t)(q0 + qrow) * SPLITS + sb) * 64 + (size_t)qq * 16;
#pragma unroll
        for (int r = 0; r < KNN; ++r) { g_pd[b + r] = kd[r]; g_pi[b + r] = ki[r]; }
    }
}

// ---------------- kernel 2: approx cut -> R3-exact fp32 rescore -------------
__global__ void knn_merge_kernel(const float* __restrict__ Q,
                                 const float* __restrict__ S,
                                 float* __restrict__ out) {
    int gw   = (blockIdx.x * blockDim.x + threadIdx.x) >> 5;  // query id
    int lane = threadIdx.x & 31;
    if (gw >= NQ) return;
    const float* pd = g_pd + (size_t)gw * (SPLITS * 64);
    const int*   pi = g_pi + (size_t)gw * (SPLITS * 64);

    // 576 approx candidates -> packed (d2_bits<<32)|idx
    ull key[CPL];
#pragma unroll
    for (int j = 0; j < CPL; ++j) {
        int c = lane + j * 32;
        key[j] = ((ull)__float_as_uint(pd[c]) << 32) | (u32)pi[c];
    }
#pragma unroll
    for (int p = 0; p < CPL; ++p)
#pragma unroll
        for (int a = (p & 1); a + 1 < CPL; a += 2)
            if (key[a + 1] < key[a]) { ull tk = key[a]; key[a] = key[a + 1]; key[a + 1] = tk; }

    // extract approx top-32; lane r keeps candidate r
    u32 myidx = 0u;
#pragma unroll
    for (int r = 0; r < NCAND; ++r) {
        ull m = key[0];
#pragma unroll
        for (int o = 16; o; o >>= 1) {
            ull v = __shfl_xor_sync(0xffffffffu, m, o);
            if (v < m) m = v;
        }
        if (key[0] == m) {                 // unique winner shifts its list
#pragma unroll
            for (int a = 0; a < CPL - 1; ++a) key[a] = key[a + 1];
            key[CPL - 1] = ~0ull;
        }
        if (lane == r) myidx = (u32)m;
    }

    // ---- rescore: one candidate per lane, sequential fp32 FMA over k ----
    const float* qp = Q + (size_t)gw * FD;
    const float* sp = S + (size_t)myidx * FD;
    float dot = 0.f;
#pragma unroll 4
    for (int k = 0; k < FD; k += 4) {
        float4 qv = *(const float4*)(qp + k);
        float4 sv = *(const float4*)(sp + k);
        dot = fmaf(qv.x, sv.x, dot);
        dot = fmaf(qv.y, sv.y, dot);
        dot = fmaf(qv.z, sv.z, dot);
        dot = fmaf(qv.w, sv.w, dot);
    }
    const float q2v = g_q2[gw];
    const float s2v = g_s2[myidx];
    float d2 = fmaxf(q2v + s2v - 2.f * dot, 1e-12f);

    // ---- exact top-16 of the 32 by (d2, idx) ----
    ull k2 = ((ull)__float_as_uint(d2) << 32) | myidx;
    float find = 0.f; u32 fini = 0u;
#pragma unroll
    for (int r = 0; r < KNN; ++r) {
        ull m = k2;
#pragma unroll
        for (int o = 16; o; o >>= 1) {
            ull v = __shfl_xor_sync(0xffffffffu, m, o);
            if (v < m) m = v;
        }
        if (k2 == m) k2 = ~0ull;           // remove winner
        if (lane == r) { find = __uint_as_float((u32)(m >> 32)); fini = (u32)m; }
    }

    // ---- weights (same formula/precision as R3) ----
    float dist = sqrtf(find);
    float sim  = (lane < KNN) ? 1.f / (dist + 1e-6f) : 0.f;
    float s = sim;
#pragma unroll
    for (int o = 16; o; o >>= 1) s += __shfl_xor_sync(0xffffffffu, s, o);
    if (lane < KNN) {
        out[(size_t)gw * KNN + lane] = (float)fini;
        out[(size_t)NQ * KNN + (size_t)gw * KNN + lane] = sim / s;
    }
}

// ---------------- launch ------------------------------------------------------
extern "C" void kernel_launch(void* const* d_in, const int* in_sizes, int n_in,
                              void* d_out, int out_size) {
    (void)in_sizes; (void)n_in; (void)out_size;
    const float* Q = (const float*)d_in[0];
    const float* S = (const float*)d_in[1];
    float* out = (float*)d_out;

    const int smem_bytes = SMEM_FLOATS * 4;   // ~108.5 KB
    cudaFuncSetAttribute(knn_mma_kernel,
                         cudaFuncAttributeMaxDynamicSharedMemorySize, smem_bytes);

    knn_norms_kernel<<<(NQ * 32) / 256, 256>>>(Q, NQ, 0);
    knn_norms_kernel<<<(NS * 32) / 256, 256>>>(S, NS, 1);

    dim3 grid(NQ / BQ, SPLITS);
    knn_mma_kernel<<<grid, NTHR, smem_bytes>>>(Q, S);

    knn_merge_kernel<<<NQ / 8, 256>>>(Q, S, out);
}